// round 17
// baseline (speedup 1.0000x reference)
#include <cuda_runtime.h>
#include <cuda_bf16.h>
#include <cstdint>
#include <math.h>

#define D_MODEL 256
#define BATCH   4
#define SEQ     2048
#define HEADS   8
#define DEPTH   32
#define DFF     1024
#define TOK     (BATCH*SEQ)   // 8192
#define EPS     1e-6f

typedef unsigned long long ull;

// ---------------- mma.sync / cp.async / f32x2 helpers -----------------------
__device__ __forceinline__ uint32_t smem_u32(const void* p) {
    uint32_t a;
    asm("{ .reg .u64 t; cvta.to.shared.u64 t, %1; cvt.u32.u64 %0, t; }"
        : "=r"(a) : "l"(p));
    return a;
}
__device__ __forceinline__ void ldsm_x4(uint32_t* r, uint32_t addr) {
    asm volatile("ldmatrix.sync.aligned.m8n8.x4.shared.b16 {%0,%1,%2,%3}, [%4];"
        : "=r"(r[0]), "=r"(r[1]), "=r"(r[2]), "=r"(r[3]) : "r"(addr));
}
__device__ __forceinline__ void ldsm_x4t(uint32_t* r, uint32_t addr) {
    asm volatile("ldmatrix.sync.aligned.m8n8.x4.trans.shared.b16 {%0,%1,%2,%3}, [%4];"
        : "=r"(r[0]), "=r"(r[1]), "=r"(r[2]), "=r"(r[3]) : "r"(addr));
}
__device__ __forceinline__ void mma_bf16(float* d, const uint32_t* a,
                                         uint32_t b0, uint32_t b1) {
    asm volatile("mma.sync.aligned.m16n8k16.row.col.f32.bf16.bf16.f32 "
        "{%0,%1,%2,%3}, {%4,%5,%6,%7}, {%8,%9}, {%0,%1,%2,%3};"
        : "+f"(d[0]), "+f"(d[1]), "+f"(d[2]), "+f"(d[3])
        : "r"(a[0]), "r"(a[1]), "r"(a[2]), "r"(a[3]), "r"(b0), "r"(b1));
}
__device__ __forceinline__ uint32_t pkbf(__nv_bfloat16 a, __nv_bfloat16 b) {
    return (uint32_t)__bfloat16_as_ushort(a) | ((uint32_t)__bfloat16_as_ushort(b) << 16);
}
__device__ __forceinline__ void cpa16(uint32_t dst, const void* src) {
    asm volatile("cp.async.cg.shared.global [%0], [%1], 16;" :: "r"(dst), "l"(src));
}
__device__ __forceinline__ void cpa4(uint32_t dst, const void* src) {
    asm volatile("cp.async.ca.shared.global [%0], [%1], 4;" :: "r"(dst), "l"(src));
}
#define CP_COMMIT() asm volatile("cp.async.commit_group;" ::: "memory")

__device__ __forceinline__ ull fma2(ull a, ull b, ull c) {
    ull d; asm("fma.rn.f32x2 %0, %1, %2, %3;" : "=l"(d) : "l"(a), "l"(b), "l"(c));
    return d;
}
__device__ __forceinline__ ull add2(ull a, ull b) {
    ull d; asm("add.rn.f32x2 %0, %1, %2;" : "=l"(d) : "l"(a), "l"(b));
    return d;
}
__device__ __forceinline__ ull pack2(float lo, float hi) {
    ull d; asm("mov.b64 %0, {%1, %2};" : "=l"(d) : "f"(lo), "f"(hi));
    return d;
}
__device__ __forceinline__ float2 unpack2(ull v) {
    float lo, hi; asm("mov.b64 {%0, %1}, %2;" : "=f"(lo), "=f"(hi) : "l"(v));
    return make_float2(lo, hi);
}

// ---------------- scratch ---------------------------------------------------
__device__ float g_tmp [TOK*D_MODEL];
__device__ float g_out1[TOK*D_MODEL];
__device__ float g_qn[TOK*HEADS], g_kn[TOK*HEADS], g_vn[TOK*HEADS];
__device__ __nv_bfloat16 g_qbh[TOK*D_MODEL], g_qbl[TOK*D_MODEL];
__device__ __nv_bfloat16 g_kbh[TOK*D_MODEL], g_kbl[TOK*D_MODEL];
__device__ __nv_bfloat16 g_vbh[TOK*D_MODEL], g_vbl[TOK*D_MODEL];
__device__ __nv_bfloat16 g_xh  [TOK*D_MODEL], g_xl  [TOK*D_MODEL];
__device__ __nv_bfloat16 g_atth[TOK*D_MODEL], g_attl[TOK*D_MODEL];
__device__ __nv_bfloat16 g_o1h [TOK*D_MODEL], g_o1l [TOK*D_MODEL];
__device__ __nv_bfloat16 g_ffhh[TOK*DFF],     g_ffhl[TOK*DFF];
__device__ __nv_bfloat16 g_wqh[D_MODEL*D_MODEL], g_wql[D_MODEL*D_MODEL];
__device__ __nv_bfloat16 g_wkh[D_MODEL*D_MODEL], g_wkl[D_MODEL*D_MODEL];
__device__ __nv_bfloat16 g_wvh[D_MODEL*D_MODEL], g_wvl[D_MODEL*D_MODEL];
__device__ __nv_bfloat16 g_woh[D_MODEL*D_MODEL], g_wol[D_MODEL*D_MODEL];
__device__ __nv_bfloat16 g_f1h[D_MODEL*DFF],     g_f1l[D_MODEL*DFF];
__device__ __nv_bfloat16 g_f2h[DFF*D_MODEL],     g_f2l[DFF*D_MODEL];

// ---------------- combined hi/lo split (weights + x), one launch ------------
struct SplitJobs {
    const float*   src[7];
    __nv_bfloat16* h[7];
    __nv_bfloat16* l[7];
    long long      start[8];
};
__global__ __launch_bounds__(256) void split_all(SplitJobs J)
{
    #pragma unroll
    for (int k = 0; k < 4; k++) {
        long long c = (long long)blockIdx.x * 1024 + k * 256 + threadIdx.x;
        if (c >= J.start[7]) return;
        int s = 0;
        #pragma unroll
        for (int i = 1; i < 7; i++) if (c >= J.start[i]) s = i;
        long long i4 = c - J.start[s];
        float4 f = ((const float4*)J.src[s])[i4];
        __nv_bfloat16 h0 = __float2bfloat16(f.x), h1 = __float2bfloat16(f.y);
        __nv_bfloat16 h2 = __float2bfloat16(f.z), h3 = __float2bfloat16(f.w);
        __nv_bfloat16 l0 = __float2bfloat16(f.x - __bfloat162float(h0));
        __nv_bfloat16 l1 = __float2bfloat16(f.y - __bfloat162float(h1));
        __nv_bfloat16 l2 = __float2bfloat16(f.z - __bfloat162float(h2));
        __nv_bfloat16 l3 = __float2bfloat16(f.w - __bfloat162float(h3));
        ((uint2*)J.h[s])[i4] = make_uint2(pkbf(h0, h1), pkbf(h2, h3));
        ((uint2*)J.l[s])[i4] = make_uint2(pkbf(l0, l1), pkbf(l2, l3));
    }
}

// ---------------- bf16x3 GEMM, 64x64 tiles, 128 threads, 2-stage ------------
// Smaller tiles double the grid (small GEMMs were grid-limited at 256 blocks)
// and 38.9 KB total smem -> 5 blocks/SM, 20 warps/SM.
// mode 0: fp32 out. mode 1: bf16 hi/lo out. mode 2: + per-head norms.
struct GemmPtrs {
    const __nv_bfloat16 *bh[3], *bl[3];
    const float* bias[3];
    float* cf[3];
    __nv_bfloat16 *ch[3], *cl[3];
    float* nrm[3];
};
#define GS_AH 0
#define GS_AL 5120
#define GS_BH 10240
#define GS_BL 14848
#define GSTG  19456
#define G_TOT (2*GSTG)

__global__ __launch_bounds__(128) void gemm_bf3(
    const __nv_bfloat16* __restrict__ Ah, const __nv_bfloat16* __restrict__ Al,
    GemmPtrs P, int K, int Ntot, int relu, int mode)
{
    extern __shared__ __align__(16) char sm[];
    uint32_t smb = smem_u32(sm);

    int tid  = threadIdx.x;
    int lane = tid & 31;
    int wid  = tid >> 5;
    int wm   = wid & 1;       // 2 row-chunks of 32
    int wn   = wid >> 1;      // 2 col-chunks of 32

    int z = blockIdx.z;
    const __nv_bfloat16* Bh = P.bh[z];
    const __nv_bfloat16* Bl = P.bl[z];
    const float* bias = P.bias[z];

    int row0 = blockIdx.y * 64;
    int col0 = blockIdx.x * 64;

    float acc[2][4][4];
    #pragma unroll
    for (int a = 0; a < 2; a++)
        #pragma unroll
        for (int b = 0; b < 4; b++)
            #pragma unroll
            for (int c = 0; c < 4; c++) acc[a][b][c] = 0.f;

    int T = K >> 5;

    // A: 64 rows x 32 cols (80B padded rows). B: 32 rows x 64 cols (144B rows).
    #define LOAD_STAGE(s, k0) do {                                             \
        uint32_t _b = smb + (s) * GSTG;                                        \
        _Pragma("unroll")                                                      \
        for (int it = 0; it < 2; it++) {                                       \
            int idx = tid + it * 128;                                          \
            int r = idx >> 2, c8 = (idx & 3) << 3;                             \
            size_t ao = (size_t)(row0 + r) * K + (k0) + c8;                    \
            cpa16(_b + GS_AH + r * 80 + c8 * 2, Ah + ao);                      \
            cpa16(_b + GS_AL + r * 80 + c8 * 2, Al + ao);                      \
        }                                                                      \
        _Pragma("unroll")                                                      \
        for (int it = 0; it < 2; it++) {                                       \
            int idx = tid + it * 128;                                          \
            int rr = idx >> 3, c8 = (idx & 7) << 3;                            \
            size_t bo = (size_t)((k0) + rr) * Ntot + col0 + c8;                \
            cpa16(_b + GS_BH + rr * 144 + c8 * 2, Bh + bo);                    \
            cpa16(_b + GS_BL + rr * 144 + c8 * 2, Bl + bo);                    \
        }                                                                      \
        CP_COMMIT();                                                           \
    } while (0)

    LOAD_STAGE(0, 0);

    for (int t = 0; t < T; t++) {
        if (t + 1 < T) {
            LOAD_STAGE((t + 1) & 1, (t + 1) * 32);
            asm volatile("cp.async.wait_group 1;" ::: "memory");
        } else {
            asm volatile("cp.async.wait_group 0;" ::: "memory");
        }
        __syncthreads();

        uint32_t sb = smb + (t & 1) * GSTG;
        #pragma unroll
        for (int kk = 0; kk < 2; kk++) {
            uint32_t ah[2][4], al[2][4], bh[2][4], bl[2][4];
            int ar = lane & 15;
            int ac = kk * 16 + (lane >> 4) * 8;
            #pragma unroll
            for (int mt = 0; mt < 2; mt++) {
                uint32_t ao = sb + (wm * 32 + mt * 16 + ar) * 80 + ac * 2;
                ldsm_x4(ah[mt], ao + GS_AH);
                ldsm_x4(al[mt], ao + GS_AL);
            }
            int br = kk * 16 + (lane & 15);
            int bc = wn * 32 + (lane >> 4) * 8;
            #pragma unroll
            for (int nt = 0; nt < 2; nt++) {
                uint32_t bo = sb + br * 144 + (bc + nt * 16) * 2;
                ldsm_x4t(bh[nt], bo + GS_BH);
                ldsm_x4t(bl[nt], bo + GS_BL);
            }
            #pragma unroll
            for (int mt = 0; mt < 2; mt++)
                #pragma unroll
                for (int nt = 0; nt < 2; nt++) {
                    mma_bf16(acc[mt][2*nt],   ah[mt], bh[nt][0], bh[nt][1]);
                    mma_bf16(acc[mt][2*nt+1], ah[mt], bh[nt][2], bh[nt][3]);
                    mma_bf16(acc[mt][2*nt],   al[mt], bh[nt][0], bh[nt][1]);
                    mma_bf16(acc[mt][2*nt+1], al[mt], bh[nt][2], bh[nt][3]);
                    mma_bf16(acc[mt][2*nt],   ah[mt], bl[nt][0], bl[nt][1]);
                    mma_bf16(acc[mt][2*nt+1], ah[mt], bl[nt][2], bl[nt][3]);
                }
        }
        __syncthreads();
    }

    float* Cf = P.cf[z];
    __nv_bfloat16* Ch = P.ch[z];
    __nv_bfloat16* Cl = P.cl[z];
    int rb = row0 + wm * 32 + (lane >> 2);
    int cb = col0 + wn * 32 + (lane & 3) * 2;
    float s2n[2][2] = {{0.f, 0.f}, {0.f, 0.f}};
    #pragma unroll
    for (int mt = 0; mt < 2; mt++) {
        #pragma unroll
        for (int nt8 = 0; nt8 < 4; nt8++) {
            int gc = cb + nt8 * 8;
            float2 bb = *(const float2*)&bias[gc];
            float2 o0, o1;
            o0.x = acc[mt][nt8][0] + bb.x;
            o0.y = acc[mt][nt8][1] + bb.y;
            o1.x = acc[mt][nt8][2] + bb.x;
            o1.y = acc[mt][nt8][3] + bb.y;
            if (relu) {
                o0.x = fmaxf(o0.x, 0.f); o0.y = fmaxf(o0.y, 0.f);
                o1.x = fmaxf(o1.x, 0.f); o1.y = fmaxf(o1.y, 0.f);
            }
            int gr = rb + mt * 16;
            if (mode == 0) {
                *(float2*)&Cf[(size_t)gr * Ntot + gc] = o0;
                *(float2*)&Cf[(size_t)(gr + 8) * Ntot + gc] = o1;
            } else {
                __nv_bfloat16 h0 = __float2bfloat16(o0.x), h1 = __float2bfloat16(o0.y);
                __nv_bfloat16 h2 = __float2bfloat16(o1.x), h3 = __float2bfloat16(o1.y);
                uint32_t lw0 = pkbf(__float2bfloat16(o0.x - __bfloat162float(h0)),
                                    __float2bfloat16(o0.y - __bfloat162float(h1)));
                uint32_t lw1 = pkbf(__float2bfloat16(o1.x - __bfloat162float(h2)),
                                    __float2bfloat16(o1.y - __bfloat162float(h3)));
                *(uint32_t*)&Ch[(size_t)gr * Ntot + gc] = pkbf(h0, h1);
                *(uint32_t*)&Cl[(size_t)gr * Ntot + gc] = lw0;
                *(uint32_t*)&Ch[(size_t)(gr + 8) * Ntot + gc] = pkbf(h2, h3);
                *(uint32_t*)&Cl[(size_t)(gr + 8) * Ntot + gc] = lw1;
                if (mode == 2) {
                    s2n[mt][0] += o0.x * o0.x + o0.y * o0.y;
                    s2n[mt][1] += o1.x * o1.x + o1.y * o1.y;
                }
            }
        }
    }
    if (mode == 2) {
        float* Nrm = P.nrm[z];
        int head = blockIdx.x * 2 + wn;   // 64 cols = 2 heads of 32
        #pragma unroll
        for (int mt = 0; mt < 2; mt++)
            #pragma unroll
            for (int rh = 0; rh < 2; rh++) {
                float s = s2n[mt][rh];
                s += __shfl_xor_sync(0xffffffffu, s, 1);
                s += __shfl_xor_sync(0xffffffffu, s, 2);
                if ((lane & 3) == 0) {
                    int gr = rb + mt * 16 + rh * 8;
                    Nrm[(size_t)gr * HEADS + head] = -0.5f * s;
                }
            }
    }
}

// ---------------- tensor-core RBF flash attention ---------------------------
// Scores = Q*Kh with Q = Qh+Ql (QKl residue cancels in softmax). P stays in
// registers (score accumulator fragment == PV A-fragment).
#define AT_KH 0
#define AT_VH 5120
#define AT_K2 10240
#define AT_STG 10496
#define AT_TOT (2*AT_STG)       // 20992

__global__ __launch_bounds__(128, 4) void attn_mma(
    const __nv_bfloat16* __restrict__ Qbh, const __nv_bfloat16* __restrict__ Qbl,
    const __nv_bfloat16* __restrict__ Kbh,
    const __nv_bfloat16* __restrict__ Vbh,
    const float* __restrict__ Qn, const float* __restrict__ Kn,
    __nv_bfloat16* __restrict__ Oh, __nv_bfloat16* __restrict__ Ol)
{
    extern __shared__ __align__(16) char sm[];
    uint32_t smb = smem_u32(sm);

    int tid = threadIdx.x, lane = tid & 31, wid = tid >> 5;
    int bh = blockIdx.y, b = bh >> 3, h = bh & 7;
    int q0 = blockIdx.x * 128;

    #define LOADKV(kt, s) do {                                                 \
        uint32_t _b = smb + (s) * AT_STG;                                      \
        _Pragma("unroll")                                                      \
        for (int it = 0; it < 2; it++) {                                       \
            int idx = tid + it * 128;                                          \
            int r = idx >> 2, c = idx & 3;                                     \
            size_t go = (size_t)(b*SEQ + (kt)*64 + r)*D_MODEL + h*DEPTH + c*8; \
            cpa16(_b + AT_KH + r * 80 + c * 16, Kbh + go);                     \
            cpa16(_b + AT_VH + r * 80 + c * 16, Vbh + go);                     \
        }                                                                      \
        if (tid < 64)                                                          \
            cpa4(_b + AT_K2 + tid * 4,                                         \
                 Kn + (size_t)(b*SEQ + (kt)*64 + tid) * HEADS + h);            \
        CP_COMMIT();                                                           \
    } while (0)

    LOADKV(0, 0);

    // Q fragments via direct LDG (mma A-fragment layout)
    uint32_t qah[2][2][4], qal[2][2][4];
    {
        int frow = lane >> 2;
        int fcol = (lane & 3) * 2;
        #pragma unroll
        for (int mt = 0; mt < 2; mt++)
            #pragma unroll
            for (int kc = 0; kc < 2; kc++) {
                size_t base = (size_t)(b*SEQ + q0 + wid*32 + mt*16 + frow) * D_MODEL
                            + h*DEPTH + kc*16 + fcol;
                qah[mt][kc][0] = *(const uint32_t*)(Qbh + base);
                qah[mt][kc][1] = *(const uint32_t*)(Qbh + base + 8*D_MODEL);
                qah[mt][kc][2] = *(const uint32_t*)(Qbh + base + 8);
                qah[mt][kc][3] = *(const uint32_t*)(Qbh + base + 8*D_MODEL + 8);
                qal[mt][kc][0] = *(const uint32_t*)(Qbl + base);
                qal[mt][kc][1] = *(const uint32_t*)(Qbl + base + 8*D_MODEL);
                qal[mt][kc][2] = *(const uint32_t*)(Qbl + base + 8);
                qal[mt][kc][3] = *(const uint32_t*)(Qbl + base + 8*D_MODEL + 8);
            }
    }
    float q2r[2][2];
    #pragma unroll
    for (int mt = 0; mt < 2; mt++)
        #pragma unroll
        for (int rh = 0; rh < 2; rh++)
            q2r[mt][rh] = Qn[(size_t)(b*SEQ + q0 + wid*32 + mt*16 + rh*8 + (lane >> 2))
                             * HEADS + h];

    // degree-4 Taylor@0.5 for e^w, w in (0,1]
    const ull C4 = pack2(0.0686967196f, 0.0686967196f);
    const ull C3 = pack2(0.274786878f,  0.274786878f);
    const ull C2 = pack2(0.824360635f,  0.824360635f);
    const ull C1 = pack2(1.64872127f,   1.64872127f);
    const ull C0 = C1;
    const ull NH = pack2(-0.5f, -0.5f);

    float oacc[2][4][4];
    #pragma unroll
    for (int a = 0; a < 2; a++)
        #pragma unroll
        for (int c = 0; c < 4; c++)
            #pragma unroll
            for (int d = 0; d < 4; d++) oacc[a][c][d] = 0.f;
    float dpart[2][2] = {{0.f, 0.f}, {0.f, 0.f}};

    for (int kt = 0; kt < SEQ / 64; kt++) {
        if (kt + 1 < SEQ / 64) {
            LOADKV(kt + 1, (kt + 1) & 1);
            asm volatile("cp.async.wait_group 1;" ::: "memory");
        } else {
            asm volatile("cp.async.wait_group 0;" ::: "memory");
        }
        __syncthreads();

        uint32_t kf = smb + (kt & 1) * AT_STG;
        float* k2s = (float*)(sm + (kt & 1) * AT_STG + AT_K2);
        int ar = lane & 15, ag = (lane >> 4) * 8;

        #pragma unroll
        for (int mt = 0; mt < 2; mt++) {
            uint32_t pa[4][4];
            #pragma unroll
            for (int ntp = 0; ntp < 4; ntp++) {
                uint32_t kbh[2][4];
                #pragma unroll
                for (int kc = 0; kc < 2; kc++)
                    ldsm_x4(kbh[kc], kf + AT_KH + (ntp*16 + ar) * 80 + (kc*16 + ag) * 2);
                #pragma unroll
                for (int nt = 0; nt < 2; nt++) {
                    float s[4] = {0.f, 0.f, 0.f, 0.f};
                    #pragma unroll
                    for (int kc = 0; kc < 2; kc++) {
                        mma_bf16(s, qah[mt][kc], kbh[kc][nt], kbh[kc][nt+2]);
                        mma_bf16(s, qal[mt][kc], kbh[kc][nt], kbh[kc][nt+2]);
                    }
                    int cbase = ntp*16 + nt*8 + (lane & 3)*2;
                    float k2c0 = k2s[cbase], k2c1 = k2s[cbase + 1];
                    #pragma unroll
                    for (int rh = 0; rh < 2; rh++) {
                        float w0 = __expf(s[rh*2+0] + q2r[mt][rh] + k2c0);
                        float w1 = __expf(s[rh*2+1] + q2r[mt][rh] + k2c1);
                        ull t = add2(pack2(w0, w1), NH);
                        ull p = fma2(C4, t, C3);
                        p = fma2(p, t, C2);
                        p = fma2(p, t, C1);
                        p = fma2(p, t, C0);
                        float2 pf = unpack2(p);
                        dpart[mt][rh] += pf.x + pf.y;
                        __nv_bfloat162 hp = __float22bfloat162_rn(pf);
                        pa[ntp][nt*2 + rh] = *(uint32_t*)&hp;
                    }
                }
            }
            #pragma unroll
            for (int kc = 0; kc < 4; kc++) {
                uint32_t vbh[2][4];
                #pragma unroll
                for (int ntp = 0; ntp < 2; ntp++)
                    ldsm_x4t(vbh[ntp], kf + AT_VH + (kc*16 + ar) * 80 + (ntp*16 + ag) * 2);
                #pragma unroll
                for (int ntp = 0; ntp < 2; ntp++)
                    #pragma unroll
                    for (int nt = 0; nt < 2; nt++)
                        mma_bf16(oacc[mt][ntp*2 + nt], pa[kc],
                                 vbh[ntp][2*nt], vbh[ntp][2*nt+1]);
            }
        }
        __syncthreads();
    }

    #pragma unroll
    for (int mt = 0; mt < 2; mt++)
        #pragma unroll
        for (int rh = 0; rh < 2; rh++) {
            float den = dpart[mt][rh];
            den += __shfl_xor_sync(0xffffffffu, den, 1);
            den += __shfl_xor_sync(0xffffffffu, den, 2);
            float inv = 1.f / den;
            int row = q0 + wid*32 + mt*16 + rh*8 + (lane >> 2);
            size_t obase = (size_t)(b*SEQ + row)*D_MODEL + h*DEPTH + (lane & 3)*2;
            #pragma unroll
            for (int nt4 = 0; nt4 < 4; nt4++) {
                float ox = oacc[mt][nt4][rh*2+0] * inv;
                float oy = oacc[mt][nt4][rh*2+1] * inv;
                __nv_bfloat16 h0 = __float2bfloat16(ox), h1 = __float2bfloat16(oy);
                uint32_t hw = pkbf(h0, h1);
                uint32_t lw = pkbf(__float2bfloat16(ox - __bfloat162float(h0)),
                                   __float2bfloat16(oy - __bfloat162float(h1)));
                *(uint32_t*)(Oh + obase + nt4*8) = hw;
                *(uint32_t*)(Ol + obase + nt4*8) = lw;
            }
        }
}

// ---------------- fused residual + LayerNorm (warp per row) -----------------
__global__ __launch_bounds__(256) void residual_ln(
    const float* __restrict__ X, const float* __restrict__ Y,
    const float* __restrict__ g, const float* __restrict__ b,
    float* __restrict__ outf,
    __nv_bfloat16* __restrict__ outh, __nv_bfloat16* __restrict__ outl,
    int do_split)
{
    int lane = threadIdx.x & 31, w = threadIdx.x >> 5;
    int row  = blockIdx.x * 8 + w;
    size_t base = (size_t)row * D_MODEL;
    int c0 = lane * 4, c1 = 128 + lane * 4;

    float4 x0 = *(const float4*)(X + base + c0);
    float4 x1 = *(const float4*)(X + base + c1);
    float4 y0 = *(const float4*)(Y + base + c0);
    float4 y1 = *(const float4*)(Y + base + c1);
    float4 v0 = make_float4(x0.x+y0.x, x0.y+y0.y, x0.z+y0.z, x0.w+y0.w);
    float4 v1 = make_float4(x1.x+y1.x, x1.y+y1.y, x1.z+y1.z, x1.w+y1.w);

    float s = v0.x+v0.y+v0.z+v0.w + v1.x+v1.y+v1.z+v1.w;
    #pragma unroll
    for (int o = 16; o > 0; o >>= 1) s += __shfl_xor_sync(0xffffffffu, s, o);
    float mean = s * (1.f / D_MODEL);

    float4 d0 = make_float4(v0.x-mean, v0.y-mean, v0.z-mean, v0.w-mean);
    float4 d1 = make_float4(v1.x-mean, v1.y-mean, v1.z-mean, v1.w-mean);
    float s2 = d0.x*d0.x+d0.y*d0.y+d0.z*d0.z+d0.w*d0.w
             + d1.x*d1.x+d1.y*d1.y+d1.z*d1.z+d1.w*d1.w;
    #pragma unroll
    for (int o = 16; o > 0; o >>= 1) s2 += __shfl_xor_sync(0xffffffffu, s2, o);
    float rstd = rsqrtf(s2 * (1.f / D_MODEL) + EPS);

    float4 g0 = *(const float4*)(g + c0), g1 = *(const float4*)(g + c1);
    float4 b0 = *(const float4*)(b + c0), b1 = *(const float4*)(b + c1);
    float4 o0, o1;
    o0.x = d0.x*rstd*g0.x + b0.x; o0.y = d0.y*rstd*g0.y + b0.y;
    o0.z = d0.z*rstd*g0.z + b0.z; o0.w = d0.w*rstd*g0.w + b0.w;
    o1.x = d1.x*rstd*g1.x + b1.x; o1.y = d1.y*rstd*g1.y + b1.y;
    o1.z = d1.z*rstd*g1.z + b1.z; o1.w = d1.w*rstd*g1.w + b1.w;
    *(float4*)(outf + base + c0) = o0;
    *(float4*)(outf + base + c1) = o1;

    if (do_split) {
        __nv_bfloat16 h0 = __float2bfloat16(o0.x), h1 = __float2bfloat16(o0.y);
        __nv_bfloat16 h2 = __float2bfloat16(o0.z), h3 = __float2bfloat16(o0.w);
        __nv_bfloat16 h4 = __float2bfloat16(o1.x), h5 = __float2bfloat16(o1.y);
        __nv_bfloat16 h6 = __float2bfloat16(o1.z), h7 = __float2bfloat16(o1.w);
        *(uint2*)(outh + base + c0) = make_uint2(pkbf(h0,h1), pkbf(h2,h3));
        *(uint2*)(outh + base + c1) = make_uint2(pkbf(h4,h5), pkbf(h6,h7));
        *(uint2*)(outl + base + c0) = make_uint2(
            pkbf(__float2bfloat16(o0.x-__bfloat162float(h0)),
                 __float2bfloat16(o0.y-__bfloat162float(h1))),
            pkbf(__float2bfloat16(o0.z-__bfloat162float(h2)),
                 __float2bfloat16(o0.w-__bfloat162float(h3))));
        *(uint2*)(outl + base + c1) = make_uint2(
            pkbf(__float2bfloat16(o1.x-__bfloat162float(h4)),
                 __float2bfloat16(o1.y-__bfloat162float(h5))),
            pkbf(__float2bfloat16(o1.z-__bfloat162float(h6)),
                 __float2bfloat16(o1.w-__bfloat162float(h7))));
    }
}

// ---------------- launch -----------------------------------------------------
extern "C" void kernel_launch(void* const* d_in, const int* in_sizes, int n_in,
                              void* d_out, int out_size)
{
    const float* x      = (const float*)d_in[0];
    const float* wq_w   = (const float*)d_in[1];
    const float* wq_b   = (const float*)d_in[2];
    const float* wk_w   = (const float*)d_in[3];
    const float* wk_b   = (const float*)d_in[4];
    const float* wv_w   = (const float*)d_in[5];
    const float* wv_b   = (const float*)d_in[6];
    const float* wo_w   = (const float*)d_in[7];
    const float* wo_b   = (const float*)d_in[8];
    const float* ffn1_w = (const float*)d_in[9];
    const float* ffn1_b = (const float*)d_in[10];
    const float* ffn2_w = (const float*)d_in[11];
    const float* ffn2_b = (const float*)d_in[12];
    const float* ln1_g  = (const float*)d_in[13];
    const float* ln1_b  = (const float*)d_in[14];
    const float* ln2_g  = (const float*)d_in[15];
    const float* ln2_b  = (const float*)d_in[16];

    float *tmp, *out1, *qn, *kn, *vn;
    cudaGetSymbolAddress((void**)&tmp,  g_tmp);
    cudaGetSymbolAddress((void**)&out1, g_out1);
    cudaGetSymbolAddress((void**)&qn,   g_qn);
    cudaGetSymbolAddress((void**)&kn,   g_kn);
    cudaGetSymbolAddress((void**)&vn,   g_vn);

    __nv_bfloat16 *qbh, *qbl, *kbh, *kbl, *vbh, *vbl;
    cudaGetSymbolAddress((void**)&qbh, g_qbh); cudaGetSymbolAddress((void**)&qbl, g_qbl);
    cudaGetSymbolAddress((void**)&kbh, g_kbh); cudaGetSymbolAddress((void**)&kbl, g_kbl);
    cudaGetSymbolAddress((void**)&vbh, g_vbh); cudaGetSymbolAddress((void**)&vbl, g_vbl);

    __nv_bfloat16 *xh, *xl, *atth, *attl, *o1h, *o1l, *ffhh, *ffhl;
    cudaGetSymbolAddress((void**)&xh,   g_xh);   cudaGetSymbolAddress((void**)&xl,   g_xl);
    cudaGetSymbolAddress((void**)&atth, g_atth); cudaGetSymbolAddress((void**)&attl, g_attl);
    cudaGetSymbolAddress((void**)&o1h,  g_o1h);  cudaGetSymbolAddress((void**)&o1l,  g_o1l);
    cudaGetSymbolAddress((void**)&ffhh, g_ffhh); cudaGetSymbolAddress((void**)&ffhl, g_ffhl);

    __nv_bfloat16 *wqh, *wql, *wkh, *wkl, *wvh, *wvl, *woh, *wol, *f1h, *f1l, *f2h, *f2l;
    cudaGetSymbolAddress((void**)&wqh, g_wqh); cudaGetSymbolAddress((void**)&wql, g_wql);
    cudaGetSymbolAddress((void**)&wkh, g_wkh); cudaGetSymbolAddress((void**)&wkl, g_wkl);
    cudaGetSymbolAddress((void**)&wvh, g_wvh); cudaGetSymbolAddress((void**)&wvl, g_wvl);
    cudaGetSymbolAddress((void**)&woh, g_woh); cudaGetSymbolAddress((void**)&wol, g_wol);
    cudaGetSymbolAddress((void**)&f1h, g_f1h); cudaGetSymbolAddress((void**)&f1l, g_f1l);
    cudaGetSymbolAddress((void**)&f2h, g_f2h); cudaGetSymbolAddress((void**)&f2l, g_f2l);

    cudaFuncSetAttribute(attn_mma, cudaFuncAttributeMaxDynamicSharedMemorySize, AT_TOT);
    cudaFuncSetAttribute(gemm_bf3, cudaFuncAttributeMaxDynamicSharedMemorySize, G_TOT);

    // one combined split launch: 6 weights + x (4 float4 per thread)
    SplitJobs J;
    const float* srcs[7] = {wq_w, wk_w, wv_w, wo_w, ffn1_w, ffn2_w, x};
    __nv_bfloat16* hs[7] = {wqh, wkh, wvh, woh, f1h, f2h, xh};
    __nv_bfloat16* ls[7] = {wql, wkl, wvl, wol, f1l, f2l, xl};
    long long sizes4[7] = {65536/4, 65536/4, 65536/4, 65536/4,
                           262144/4, 262144/4, (long long)TOK*D_MODEL/4};
    long long acc = 0;
    for (int i = 0; i < 7; i++) { J.src[i] = srcs[i]; J.h[i] = hs[i]; J.l[i] = ls[i];
                                  J.start[i] = acc; acc += sizes4[i]; }
    J.start[7] = acc;
    split_all<<<(unsigned)((acc + 1023) / 1024), 256>>>(J);

    // QKV projections: bf16 hi/lo out + head norms (mode 2)
    {
        GemmPtrs P = {};
        P.bh[0] = wqh; P.bl[0] = wql; P.bias[0] = wq_b;
        P.bh[1] = wkh; P.bl[1] = wkl; P.bias[1] = wk_b;
        P.bh[2] = wvh; P.bl[2] = wvl; P.bias[2] = wv_b;
        P.ch[0] = qbh; P.cl[0] = qbl; P.nrm[0] = qn;
        P.ch[1] = kbh; P.cl[1] = kbl; P.nrm[1] = kn;
        P.ch[2] = vbh; P.cl[2] = vbl; P.nrm[2] = vn;
        gemm_bf3<<<dim3(4, 128, 3), 128, G_TOT>>>(xh, xl, P, D_MODEL, D_MODEL, 0, 2);
    }

    // tensor-core RBF attention
    attn_mma<<<dim3(SEQ / 128, BATCH * HEADS), 128, AT_TOT>>>(
        qbh, qbl, kbh, vbh, qn, kn, atth, attl);

    // output projection (fp32) + residual LN1
    {
        GemmPtrs P = {};
        P.bh[0] = woh; P.bl[0] = wol; P.bias[0] = wo_b; P.cf[0] = tmp;
        gemm_bf3<<<dim3(4, 128, 1), 128, G_TOT>>>(atth, attl, P, D_MODEL, D_MODEL, 0, 0);
    }
    residual_ln<<<TOK / 8, 256>>>(x, tmp, ln1_g, ln1_b, out1, o1h, o1l, 1);

    // FFN1 (relu, bf16 out) -> FFN2 (fp32) -> residual LN2
    {
        GemmPtrs P = {};
        P.bh[0] = f1h; P.bl[0] = f1l; P.bias[0] = ffn1_b;
        P.ch[0] = ffhh; P.cl[0] = ffhl;
        gemm_bf3<<<dim3(16, 128, 1), 128, G_TOT>>>(o1h, o1l, P, D_MODEL, DFF, 1, 1);
    }
    {
        GemmPtrs P = {};
        P.bh[0] = f2h; P.bl[0] = f2l; P.bias[0] = ffn2_b; P.cf[0] = tmp;
        gemm_bf3<<<dim3(4, 128, 1), 128, G_TOT>>>(ffhh, ffhl, P, DFF, D_MODEL, 0, 0);
    }
    residual_ln<<<TOK / 8, 256>>>(out1, tmp, ln2_g, ln2_b, (float*)d_out,
                                  (__nv_bfloat16*)0, (__nv_bfloat16*)0, 0);
}